// round 6
// baseline (speedup 1.0000x reference)
#include <cuda_runtime.h>

#define IMG_H 512
#define IMG_W 512
#define TX 32
#define TY 32
#define HALO 5
#define IN_W 42              // TX + 2*HALO
#define IN_H 42              // TY + 2*HALO
#define SP 43                // sxy row stride in float2 slots (43 mod 16 = 11 -> conflict-free)
#define HP 33                // H row stride in float2 slots (33 mod 16 = 1 -> conflict-free)
#define NT 384

#define C1V 1.0e-4f
#define C2V 9.0e-4f
#define EPSV 1.0e-8f

// Normalized 1D Gaussian, sigma=1.5, window 11 (symmetric). Compile-time
// constants -> FFMA with immediate multiplier (rt_SMSP=1 on sm_10x).
__device__ constexpr float GW[11] = {
    0.00102838f, 0.00759876f, 0.03600077f, 0.10936069f, 0.21300553f,
    0.26601172f,
    0.21300553f, 0.10936069f, 0.03600077f, 0.00759876f, 0.00102838f
};

__global__ void zero_out_kernel(float* out) { out[0] = 0.0f; }

__global__ __launch_bounds__(NT, 4) void ssim_kernel(
    const float* __restrict__ x, const float* __restrict__ y,
    float* __restrict__ out, float inv_n)
{
    // Sum/difference transform: convolve s=x+y, d=x-y -> only 4 maps needed.
    __shared__ float2 sxy[IN_H * SP];    // (s, d)       14.4 KB
    __shared__ float2 Hsd[IN_H * HP];    // (Hs, Hd)     11.1 KB
    __shared__ float2 Hs2[IN_H * HP];    // (Hss, Hdd)   11.1 KB
    __shared__ float  red[12];

    const int tid = threadIdx.x;
    const int x0 = blockIdx.x * TX - HALO;
    const int y0 = blockIdx.y * TY - HALO;
    const size_t imgoff = (size_t)blockIdx.z * (IMG_H * IMG_W);
    const float* xb = x + imgoff;
    const float* yb = y + imgoff;

    // ---- Phase 1: load halo tile, store (s,d) pairs ----
    const bool interior = (x0 >= 0) & (y0 >= 0) &
                          (x0 + IN_W <= IMG_W) & (y0 + IN_H <= IMG_H);
    if (interior) {
        #pragma unroll
        for (int it = 0; it < 5; it++) {
            int idx = tid + it * NT;
            if (idx < IN_H * IN_W) {          // 1764 total
                int r = idx / IN_W;
                int c = idx - r * IN_W;
                int g = (y0 + r) * IMG_W + (x0 + c);
                float xv = __ldg(xb + g);
                float yv = __ldg(yb + g);
                sxy[r * SP + c] = make_float2(xv + yv, xv - yv);
            }
        }
    } else {
        #pragma unroll
        for (int it = 0; it < 5; it++) {
            int idx = tid + it * NT;
            if (idx < IN_H * IN_W) {
                int r = idx / IN_W;
                int c = idx - r * IN_W;
                int gy = y0 + r, gx = x0 + c;
                float sv = 0.0f, dv = 0.0f;
                if (gy >= 0 && gy < IMG_H && gx >= 0 && gx < IMG_W) {
                    int g = gy * IMG_W + gx;
                    float xv = __ldg(xb + g);
                    float yv = __ldg(yb + g);
                    sv = xv + yv;
                    dv = xv - yv;
                }
                sxy[r * SP + c] = make_float2(sv, dv);
            }
        }
    }
    __syncthreads();

    // ---- Phase 2: horizontal pass, two half-passes on DISJOINT warp sets ----
    // Half-pass A (mean maps):   threads [0, 168)   -> warps 0-5
    // Half-pass B (2nd moments): threads [192, 360) -> warps 6-11
    // No warp contains both -> halves run concurrently, not serialized.
    if (tid < IN_H * 4) {
        const int cg  = tid / IN_H;          // 0..3 (8-col groups)
        const int row = tid - cg * IN_H;     // 0..41
        const float2* pin = sxy + row * SP + cg * 8;
        float as[8], ad[8];
        #pragma unroll
        for (int i = 0; i < 18; i++) {
            float2 v = pin[i];
            #pragma unroll
            for (int k = 0; k < 8; k++) {
                const int d = i - k;
                if (d == 0) {                 // first tap: mul-init
                    as[k] = v.x * GW[0];
                    ad[k] = v.y * GW[0];
                } else if (d > 0 && d <= 10) {
                    const float w = GW[d];
                    as[k] = fmaf(v.x, w, as[k]);
                    ad[k] = fmaf(v.y, w, ad[k]);
                }
            }
        }
        const int hb = row * HP + cg * 8;
        #pragma unroll
        for (int k = 0; k < 8; k++) Hsd[hb + k] = make_float2(as[k], ad[k]);
    } else if (tid >= 192 && tid < 192 + IN_H * 4) {
        const int u   = tid - 192;
        const int cg  = u / IN_H;
        const int row = u - cg * IN_H;
        const float2* pin = sxy + row * SP + cg * 8;
        float as2[8], ad2[8];
        #pragma unroll
        for (int i = 0; i < 18; i++) {
            float2 v = pin[i];
            float ss = v.x * v.x;
            float dd = v.y * v.y;
            #pragma unroll
            for (int k = 0; k < 8; k++) {
                const int d = i - k;
                if (d == 0) {
                    as2[k] = ss * GW[0];
                    ad2[k] = dd * GW[0];
                } else if (d > 0 && d <= 10) {
                    const float w = GW[d];
                    as2[k] = fmaf(ss, w, as2[k]);
                    ad2[k] = fmaf(dd, w, ad2[k]);
                }
            }
        }
        const int hb = row * HP + cg * 8;
        #pragma unroll
        for (int k = 0; k < 8; k++) Hs2[hb + k] = make_float2(as2[k], ad2[k]);
    }
    __syncthreads();

    // ---- Phase 3: vertical pass + SSIM ----
    // 12 warps cover 32 rows: warps 0-7 take 3 rows, warps 8-11 take 2 rows.
    const int c  = tid & 31;
    const int rg = tid >> 5;
    float lsum = 0.0f;

    if (rg < 8) {
        const int rbase = rg * 3;
        float ms[3], md[3], mss[3], mdd[3];
        const float2* p1 = Hsd + rbase * HP + c;
        const float2* p2 = Hs2 + rbase * HP + c;
        #pragma unroll
        for (int j = 0; j < 13; j++) {
            float2 h1 = p1[j * HP];
            float2 h2 = p2[j * HP];
            #pragma unroll
            for (int k = 0; k < 3; k++) {
                const int d = j - k;
                if (d == 0) {
                    ms[k]  = h1.x * GW[0];
                    md[k]  = h1.y * GW[0];
                    mss[k] = h2.x * GW[0];
                    mdd[k] = h2.y * GW[0];
                } else if (d > 0 && d <= 10) {
                    const float w = GW[d];
                    ms[k]  = fmaf(h1.x, w, ms[k]);
                    md[k]  = fmaf(h1.y, w, md[k]);
                    mss[k] = fmaf(h2.x, w, mss[k]);
                    mdd[k] = fmaf(h2.y, w, mdd[k]);
                }
            }
        }
        #pragma unroll
        for (int k = 0; k < 3; k++) {
            float mus = ms[k],  mud = md[k];
            float ess = mss[k], edd = mdd[k];
            float mus2 = mus * mus, mud2 = mud * mud;
            float muxy    = 0.25f * (mus2 - mud2);
            float mux2py2 = 0.5f  * (mus2 + mud2);
            float exy     = 0.25f * (ess - edd);
            float exxpyy  = 0.5f  * (ess + edd);
            float sxyv  = exy - muxy;
            float sxpsy = exxpyy - mux2py2;
            float n = (2.0f * muxy + C1V) * (2.0f * sxyv + C2V);
            float den = (mux2py2 + C1V) * (sxpsy + C2V) + EPSV;
            float v = (1.0f + __fdividef(n, den)) * 0.5f;
            lsum += fminf(fmaxf(v, 0.0f), 1.0f);
        }
    } else {
        const int rbase = 24 + (rg - 8) * 2;
        float ms[2], md[2], mss[2], mdd[2];
        const float2* p1 = Hsd + rbase * HP + c;
        const float2* p2 = Hs2 + rbase * HP + c;
        #pragma unroll
        for (int j = 0; j < 12; j++) {
            float2 h1 = p1[j * HP];
            float2 h2 = p2[j * HP];
            #pragma unroll
            for (int k = 0; k < 2; k++) {
                const int d = j - k;
                if (d == 0) {
                    ms[k]  = h1.x * GW[0];
                    md[k]  = h1.y * GW[0];
                    mss[k] = h2.x * GW[0];
                    mdd[k] = h2.y * GW[0];
                } else if (d > 0 && d <= 10) {
                    const float w = GW[d];
                    ms[k]  = fmaf(h1.x, w, ms[k]);
                    md[k]  = fmaf(h1.y, w, md[k]);
                    mss[k] = fmaf(h2.x, w, mss[k]);
                    mdd[k] = fmaf(h2.y, w, mdd[k]);
                }
            }
        }
        #pragma unroll
        for (int k = 0; k < 2; k++) {
            float mus = ms[k],  mud = md[k];
            float ess = mss[k], edd = mdd[k];
            float mus2 = mus * mus, mud2 = mud * mud;
            float muxy    = 0.25f * (mus2 - mud2);
            float mux2py2 = 0.5f  * (mus2 + mud2);
            float exy     = 0.25f * (ess - edd);
            float exxpyy  = 0.5f  * (ess + edd);
            float sxyv  = exy - muxy;
            float sxpsy = exxpyy - mux2py2;
            float n = (2.0f * muxy + C1V) * (2.0f * sxyv + C2V);
            float den = (mux2py2 + C1V) * (sxpsy + C2V) + EPSV;
            float v = (1.0f + __fdividef(n, den)) * 0.5f;
            lsum += fminf(fmaxf(v, 0.0f), 1.0f);
        }
    }

    // ---- Reduction: warp shuffle -> smem -> block -> atomic ----
    #pragma unroll
    for (int off = 16; off > 0; off >>= 1)
        lsum += __shfl_xor_sync(0xFFFFFFFFu, lsum, off);
    if ((tid & 31) == 0) red[tid >> 5] = lsum;
    __syncthreads();
    if (tid == 0) {
        float t = 0.0f;
        #pragma unroll
        for (int w = 0; w < 12; w++) t += red[w];
        atomicAdd(out, t * inv_n);
    }
}

extern "C" void kernel_launch(void* const* d_in, const int* in_sizes, int n_in,
                              void* d_out, int out_size)
{
    const float* x = (const float*)d_in[0];
    const float* y = (const float*)d_in[1];
    float* out = (float*)d_out;

    zero_out_kernel<<<1, 1>>>(out);

    dim3 grid(IMG_W / TX, IMG_H / TY, 16 * 3);   // 16 x 16 x 48
    const float inv_n = 1.0f / (float)(16 * 3 * IMG_H * IMG_W);
    ssim_kernel<<<grid, NT>>>(x, y, out, inv_n);
}

// round 7
// speedup vs baseline: 1.0652x; 1.0652x over previous
#include <cuda_runtime.h>

#define IMG_H 512
#define IMG_W 512
#define TX 32
#define TY 32
#define HALO 5
#define IN_W 42              // TX + 2*HALO
#define IN_H 42              // TY + 2*HALO
#define SP 43                // sxy row stride in float2 slots (43 mod 16 = 11 -> conflict-free)
#define HP 33                // H row stride in float2 slots (33 mod 16 = 1 -> conflict-free)
#define NT 256

#define C1V 1.0e-4f
#define C2V 9.0e-4f
#define EPSV 1.0e-8f

// Normalized 1D Gaussian, sigma=1.5, window 11 (symmetric). Compile-time
// constants -> FFMA with immediate multiplier (rt_SMSP=1 on sm_10x).
__device__ constexpr float GW[11] = {
    0.00102838f, 0.00759876f, 0.03600077f, 0.10936069f, 0.21300553f,
    0.26601172f,
    0.21300553f, 0.10936069f, 0.03600077f, 0.00759876f, 0.00102838f
};

__global__ void zero_out_kernel(float* out) { out[0] = 0.0f; }

__global__ __launch_bounds__(NT, 4) void ssim_kernel(
    const float* __restrict__ x, const float* __restrict__ y,
    float* __restrict__ out, float inv_n)
{
    // Sum/difference transform: convolve s=x+y, d=x-y -> only 4 maps needed.
    __shared__ float2 sxy[IN_H * SP];    // (s, d)       14.4 KB
    __shared__ float2 Hsd[IN_H * HP];    // (Hs, Hd)     11.1 KB
    __shared__ float2 Hs2[IN_H * HP];    // (Hss, Hdd)   11.1 KB
    __shared__ float  red[8];

    const int tid = threadIdx.x;
    const int x0 = blockIdx.x * TX - HALO;
    const int y0 = blockIdx.y * TY - HALO;
    const size_t imgoff = (size_t)blockIdx.z * (IMG_H * IMG_W);
    const float* xb = x + imgoff;
    const float* yb = y + imgoff;

    // ---- Phase 1: load halo tile, store (s,d) pairs ----
    const bool interior = (x0 >= 0) & (y0 >= 0) &
                          (x0 + IN_W <= IMG_W) & (y0 + IN_H <= IMG_H);
    if (interior) {
        #pragma unroll
        for (int it = 0; it < 7; it++) {
            int idx = tid + it * NT;
            if (idx < IN_H * IN_W) {          // 1764 total
                int r = idx / IN_W;
                int c = idx - r * IN_W;
                int g = (y0 + r) * IMG_W + (x0 + c);
                float xv = __ldg(xb + g);
                float yv = __ldg(yb + g);
                sxy[r * SP + c] = make_float2(xv + yv, xv - yv);
            }
        }
    } else {
        #pragma unroll
        for (int it = 0; it < 7; it++) {
            int idx = tid + it * NT;
            if (idx < IN_H * IN_W) {
                int r = idx / IN_W;
                int c = idx - r * IN_W;
                int gy = y0 + r, gx = x0 + c;
                float sv = 0.0f, dv = 0.0f;
                if (gy >= 0 && gy < IMG_H && gx >= 0 && gx < IMG_W) {
                    int g = gy * IMG_W + gx;
                    float xv = __ldg(xb + g);
                    float yv = __ldg(yb + g);
                    sv = xv + yv;
                    dv = xv - yv;
                }
                sxy[r * SP + c] = make_float2(sv, dv);
            }
        }
    }
    __syncthreads();

    // ---- Phase 2: horizontal pass, FUSED (single load stream, 4 maps) ----
    // 168 units of 8 output cols; each pin[i] loaded exactly once.
    if (tid < IN_H * 4) {
        const int cg  = tid / IN_H;          // 0..3 (8-col groups)
        const int row = tid - cg * IN_H;     // 0..41
        const float2* pin = sxy + row * SP + cg * 8;
        float as[8], ad[8], as2[8], ad2[8];
        #pragma unroll
        for (int i = 0; i < 18; i++) {
            float2 v = pin[i];
            float ss = v.x * v.x;
            float dd = v.y * v.y;
            #pragma unroll
            for (int k = 0; k < 8; k++) {
                const int d = i - k;
                if (d == 0) {                 // first tap: mul-init (no MOV 0)
                    as[k]  = v.x * GW[0];
                    ad[k]  = v.y * GW[0];
                    as2[k] = ss  * GW[0];
                    ad2[k] = dd  * GW[0];
                } else if (d > 0 && d <= 10) {
                    const float w = GW[d];
                    as[k]  = fmaf(v.x, w, as[k]);
                    ad[k]  = fmaf(v.y, w, ad[k]);
                    as2[k] = fmaf(ss,  w, as2[k]);
                    ad2[k] = fmaf(dd,  w, ad2[k]);
                }
            }
        }
        const int hb = row * HP + cg * 8;
        #pragma unroll
        for (int k = 0; k < 8; k++) {
            Hsd[hb + k] = make_float2(as[k], ad[k]);
            Hs2[hb + k] = make_float2(as2[k], ad2[k]);
        }
    }
    __syncthreads();

    // ---- Phase 3: vertical pass + SSIM, 4 rows per thread ----
    const int c     = tid & 31;
    const int rbase = (tid >> 5) * 4;
    float ms[4], md[4], mss[4], mdd[4];
    const float2* p1 = Hsd + rbase * HP + c;
    const float2* p2 = Hs2 + rbase * HP + c;
    #pragma unroll
    for (int j = 0; j < 14; j++) {
        float2 h1 = p1[j * HP];
        float2 h2 = p2[j * HP];
        #pragma unroll
        for (int k = 0; k < 4; k++) {
            const int d = j - k;
            if (d == 0) {
                ms[k]  = h1.x * GW[0];
                md[k]  = h1.y * GW[0];
                mss[k] = h2.x * GW[0];
                mdd[k] = h2.y * GW[0];
            } else if (d > 0 && d <= 10) {
                const float w = GW[d];
                ms[k]  = fmaf(h1.x, w, ms[k]);
                md[k]  = fmaf(h1.y, w, md[k]);
                mss[k] = fmaf(h2.x, w, mss[k]);
                mdd[k] = fmaf(h2.y, w, mdd[k]);
            }
        }
    }

    float lsum = 0.0f;
    #pragma unroll
    for (int k = 0; k < 4; k++) {
        float mus = ms[k],  mud = md[k];
        float ess = mss[k], edd = mdd[k];
        float mus2 = mus * mus, mud2 = mud * mud;
        float muxy    = 0.25f * (mus2 - mud2);   // mu_x * mu_y
        float mux2py2 = 0.5f  * (mus2 + mud2);   // mu_x^2 + mu_y^2
        float exy     = 0.25f * (ess - edd);     // E[xy]
        float exxpyy  = 0.5f  * (ess + edd);     // E[x^2] + E[y^2]
        float sxyv  = exy - muxy;                // sigma_xy
        float sxpsy = exxpyy - mux2py2;          // sigma_x + sigma_y
        float n = (2.0f * muxy + C1V) * (2.0f * sxyv + C2V);
        float den = (mux2py2 + C1V) * (sxpsy + C2V) + EPSV;
        float v = (1.0f + __fdividef(n, den)) * 0.5f;
        v = fminf(fmaxf(v, 0.0f), 1.0f);
        lsum += v;
    }

    // ---- Reduction: warp shuffle -> smem -> block -> atomic ----
    #pragma unroll
    for (int off = 16; off > 0; off >>= 1)
        lsum += __shfl_xor_sync(0xFFFFFFFFu, lsum, off);
    if ((tid & 31) == 0) red[tid >> 5] = lsum;
    __syncthreads();
    if (tid == 0) {
        float t = 0.0f;
        #pragma unroll
        for (int w = 0; w < 8; w++) t += red[w];
        atomicAdd(out, t * inv_n);
    }
}

extern "C" void kernel_launch(void* const* d_in, const int* in_sizes, int n_in,
                              void* d_out, int out_size)
{
    const float* x = (const float*)d_in[0];
    const float* y = (const float*)d_in[1];
    float* out = (float*)d_out;

    zero_out_kernel<<<1, 1>>>(out);

    dim3 grid(IMG_W / TX, IMG_H / TY, 16 * 3);   // 16 x 16 x 48
    const float inv_n = 1.0f / (float)(16 * 3 * IMG_H * IMG_W);
    ssim_kernel<<<grid, NT>>>(x, y, out, inv_n);
}

// round 9
// speedup vs baseline: 1.1378x; 1.0682x over previous
#include <cuda_runtime.h>

#define IMG_H 512
#define IMG_W 512
#define TX 32
#define TY 32
#define HALO 5
#define IN_W 42              // TX + 2*HALO
#define IN_H 42              // TY + 2*HALO
#define SP 43                // sxy row stride in float2 slots (43 mod 16 = 11 -> conflict-free)
#define HP 33                // H row stride in float2 slots (33 mod 16 = 1 -> conflict-free)
#define NT 256

#define C1V 1.0e-4f
#define C2V 9.0e-4f
#define EPSV 1.0e-8f

// Normalized 1D Gaussian, sigma=1.5, window 11 (symmetric). Compile-time
// constants -> FFMA with immediate multiplier (rt_SMSP=1 on sm_10x).
__device__ constexpr float GW[11] = {
    0.00102838f, 0.00759876f, 0.03600077f, 0.10936069f, 0.21300553f,
    0.26601172f,
    0.21300553f, 0.10936069f, 0.03600077f, 0.00759876f, 0.00102838f
};

__global__ void zero_out_kernel(float* out) { out[0] = 0.0f; }

__global__ __launch_bounds__(NT, 5) void ssim_kernel(
    const float* __restrict__ x, const float* __restrict__ y,
    float* __restrict__ out, float inv_n)
{
    // Sum/difference transform: convolve s=x+y, d=x-y -> only 4 maps needed.
    __shared__ float2 sxy[IN_H * SP];    // (s, d)       14.4 KB
    __shared__ float2 Hsd[IN_H * HP];    // (Hs, Hd)     11.1 KB
    __shared__ float2 Hs2[IN_H * HP];    // (Hss, Hdd)   11.1 KB
    __shared__ float  red[8];

    const int tid = threadIdx.x;
    const int x0 = blockIdx.x * TX - HALO;
    const int y0 = blockIdx.y * TY - HALO;
    const size_t imgoff = (size_t)blockIdx.z * (IMG_H * IMG_W);
    const float* xb = x + imgoff;
    const float* yb = y + imgoff;

    // ---- Phase 1: load halo tile, store (s,d) pairs ----
    const bool interior = (x0 >= 0) & (y0 >= 0) &
                          (x0 + IN_W <= IMG_W) & (y0 + IN_H <= IMG_H);
    if (interior) {
        #pragma unroll
        for (int it = 0; it < 7; it++) {
            int idx = tid + it * NT;
            if (idx < IN_H * IN_W) {          // 1764 total
                int r = idx / IN_W;
                int c = idx - r * IN_W;
                int g = (y0 + r) * IMG_W + (x0 + c);
                float xv = __ldg(xb + g);
                float yv = __ldg(yb + g);
                sxy[r * SP + c] = make_float2(xv + yv, xv - yv);
            }
        }
    } else {
        #pragma unroll
        for (int it = 0; it < 7; it++) {
            int idx = tid + it * NT;
            if (idx < IN_H * IN_W) {
                int r = idx / IN_W;
                int c = idx - r * IN_W;
                int gy = y0 + r, gx = x0 + c;
                float sv = 0.0f, dv = 0.0f;
                if (gy >= 0 && gy < IMG_H && gx >= 0 && gx < IMG_W) {
                    int g = gy * IMG_W + gx;
                    float xv = __ldg(xb + g);
                    float yv = __ldg(yb + g);
                    sv = xv + yv;
                    dv = xv - yv;
                }
                sxy[r * SP + c] = make_float2(sv, dv);
            }
        }
    }
    __syncthreads();

    // ---- Phase 2: horizontal pass, FUSED (single load stream, 4 maps) ----
    // 168 units of 8 output cols; each pin[i] loaded exactly once.
    if (tid < IN_H * 4) {
        const int cg  = tid / IN_H;          // 0..3 (8-col groups)
        const int row = tid - cg * IN_H;     // 0..41
        const float2* pin = sxy + row * SP + cg * 8;
        float as[8], ad[8], as2[8], ad2[8];
        #pragma unroll
        for (int i = 0; i < 18; i++) {
            float2 v = pin[i];
            float ss = v.x * v.x;
            float dd = v.y * v.y;
            #pragma unroll
            for (int k = 0; k < 8; k++) {
                const int d = i - k;
                if (d == 0) {                 // first tap: mul-init (no MOV 0)
                    as[k]  = v.x * GW[0];
                    ad[k]  = v.y * GW[0];
                    as2[k] = ss  * GW[0];
                    ad2[k] = dd  * GW[0];
                } else if (d > 0 && d <= 10) {
                    const float w = GW[d];
                    as[k]  = fmaf(v.x, w, as[k]);
                    ad[k]  = fmaf(v.y, w, ad[k]);
                    as2[k] = fmaf(ss,  w, as2[k]);
                    ad2[k] = fmaf(dd,  w, ad2[k]);
                }
            }
        }
        const int hb = row * HP + cg * 8;
        #pragma unroll
        for (int k = 0; k < 8; k++) {
            Hsd[hb + k] = make_float2(as[k], ad[k]);
            Hs2[hb + k] = make_float2(as2[k], ad2[k]);
        }
    }
    __syncthreads();

    // ---- Phase 3: vertical pass + SSIM, 4 rows per thread ----
    const int c     = tid & 31;
    const int rbase = (tid >> 5) * 4;
    float ms[4], md[4], mss[4], mdd[4];
    const float2* p1 = Hsd + rbase * HP + c;
    const float2* p2 = Hs2 + rbase * HP + c;
    #pragma unroll
    for (int j = 0; j < 14; j++) {
        float2 h1 = p1[j * HP];
        float2 h2 = p2[j * HP];
        #pragma unroll
        for (int k = 0; k < 4; k++) {
            const int d = j - k;
            if (d == 0) {
                ms[k]  = h1.x * GW[0];
                md[k]  = h1.y * GW[0];
                mss[k] = h2.x * GW[0];
                mdd[k] = h2.y * GW[0];
            } else if (d > 0 && d <= 10) {
                const float w = GW[d];
                ms[k]  = fmaf(h1.x, w, ms[k]);
                md[k]  = fmaf(h1.y, w, md[k]);
                mss[k] = fmaf(h2.x, w, mss[k]);
                mdd[k] = fmaf(h2.y, w, mdd[k]);
            }
        }
    }

    // SSIM in sum/diff-native form:
    //   a = mus^2-mud^2 (=4 mux*muy)     b = mus^2+mud^2 (=2(mux^2+muy^2))
    //   e = Ess-Edd     (=4 E[xy])        f = Ess+Edd    (=2(E[x^2]+E[y^2]))
    //   2 muxy + C1   = 0.5a + C1         2 sigma_xy + C2 = 0.5(e-a) + C2
    //   mux^2+muy^2+C1= 0.5b + C1         sigma_x+sigma_y+C2 = 0.5(f-b) + C2
    float lsum = 0.0f;
    #pragma unroll
    for (int k = 0; k < 4; k++) {
        float mus = ms[k],  mud = md[k];
        float a = fmaf(mus, mus, -(mud * mud));
        float b = fmaf(mus, mus,  (mud * mud));
        float e = mss[k] - mdd[k];
        float f = mss[k] + mdd[k];
        float n   = fmaf(0.5f, a, C1V) * fmaf(0.5f, e - a, C2V);
        float den = fmaf(0.5f, b, C1V) * fmaf(0.5f, f - b, C2V) + EPSV;
        float v = fmaf(__fdividef(n, den), 0.5f, 0.5f);
        v = fminf(fmaxf(v, 0.0f), 1.0f);
        lsum += v;
    }

    // ---- Reduction: warp shuffle -> smem -> block -> atomic ----
    #pragma unroll
    for (int off = 16; off > 0; off >>= 1)
        lsum += __shfl_xor_sync(0xFFFFFFFFu, lsum, off);
    if ((tid & 31) == 0) red[tid >> 5] = lsum;
    __syncthreads();
    if (tid == 0) {
        float t = 0.0f;
        #pragma unroll
        for (int w = 0; w < 8; w++) t += red[w];
        atomicAdd(out, t * inv_n);
    }
}

extern "C" void kernel_launch(void* const* d_in, const int* in_sizes, int n_in,
                              void* d_out, int out_size)
{
    const float* x = (const float*)d_in[0];
    const float* y = (const float*)d_in[1];
    float* out = (float*)d_out;

    zero_out_kernel<<<1, 1>>>(out);

    dim3 grid(IMG_W / TX, IMG_H / TY, 16 * 3);   // 16 x 16 x 48
    const float inv_n = 1.0f / (float)(16 * 3 * IMG_H * IMG_W);
    ssim_kernel<<<grid, NT>>>(x, y, out, inv_n);
}

// round 11
// speedup vs baseline: 1.1588x; 1.0184x over previous
#include <cuda_runtime.h>

#define IMG_H 512
#define IMG_W 512
#define TX 32
#define TY 32
#define HALO 5
#define IN_W 42              // TX + 2*HALO
#define IN_H 42              // TY + 2*HALO
#define SP 43                // sxy row stride in float2 slots (43 mod 16 = 11 -> conflict-free)
#define HP 33                // H row stride in float4 slots (see bank audit in comments)
#define NT 256

#define C1V 1.0e-4f
#define C2V 9.0e-4f
#define EPSV 1.0e-8f

// Normalized 1D Gaussian, sigma=1.5, window 11 (symmetric). Compile-time
// constants -> FFMA with immediate multiplier (rt_SMSP=1 on sm_10x).
__device__ constexpr float GW[11] = {
    0.00102838f, 0.00759876f, 0.03600077f, 0.10936069f, 0.21300553f,
    0.26601172f,
    0.21300553f, 0.10936069f, 0.03600077f, 0.00759876f, 0.00102838f
};

__global__ void zero_out_kernel(float* out) { out[0] = 0.0f; }

__global__ __launch_bounds__(NT, 5) void ssim_kernel(
    const float* __restrict__ x, const float* __restrict__ y,
    float* __restrict__ out, float inv_n)
{
    // Sum/difference transform: convolve s=x+y, d=x-y -> 4 maps.
    // H maps interleaved as float4 (Hs, Hd, Hss, Hdd): one LDS.128 replaces
    // two LDS.64 in phase 3; one STS.128 replaces two STS.64 in phase 2.
    __shared__ float2 sxy[IN_H * SP];    // (s, d)               14.4 KB
    __shared__ float4 Hmap[IN_H * HP];   // (Hs, Hd, Hss, Hdd)   22.2 KB
    __shared__ float  red[8];

    const int tid = threadIdx.x;
    const int x0 = blockIdx.x * TX - HALO;
    const int y0 = blockIdx.y * TY - HALO;
    const size_t imgoff = (size_t)blockIdx.z * (IMG_H * IMG_W);
    const float* xb = x + imgoff;
    const float* yb = y + imgoff;

    // ---- Phase 1: load halo tile, store (s,d) pairs ----
    const bool interior = (x0 >= 0) & (y0 >= 0) &
                          (x0 + IN_W <= IMG_W) & (y0 + IN_H <= IMG_H);
    if (interior) {
        #pragma unroll
        for (int it = 0; it < 7; it++) {
            int idx = tid + it * NT;
            if (idx < IN_H * IN_W) {          // 1764 total
                int r = idx / IN_W;
                int c = idx - r * IN_W;
                int g = (y0 + r) * IMG_W + (x0 + c);
                float xv = __ldg(xb + g);
                float yv = __ldg(yb + g);
                sxy[r * SP + c] = make_float2(xv + yv, xv - yv);
            }
        }
    } else {
        #pragma unroll
        for (int it = 0; it < 7; it++) {
            int idx = tid + it * NT;
            if (idx < IN_H * IN_W) {
                int r = idx / IN_W;
                int c = idx - r * IN_W;
                int gy = y0 + r, gx = x0 + c;
                float sv = 0.0f, dv = 0.0f;
                if (gy >= 0 && gy < IMG_H && gx >= 0 && gx < IMG_W) {
                    int g = gy * IMG_W + gx;
                    float xv = __ldg(xb + g);
                    float yv = __ldg(yb + g);
                    sv = xv + yv;
                    dv = xv - yv;
                }
                sxy[r * SP + c] = make_float2(sv, dv);
            }
        }
    }
    __syncthreads();

    // ---- Phase 2: horizontal pass, FUSED (single load stream, 4 maps) ----
    // 168 units of 8 output cols; each pin[i] loaded exactly once.
    // Store bank audit (STS.128, 8-lane wavefronts = consecutive rows):
    // bank group = 4*((33*row + col) mod 8) -> distinct over 8 rows.
    if (tid < IN_H * 4) {
        const int cg  = tid / IN_H;          // 0..3 (8-col groups)
        const int row = tid - cg * IN_H;     // 0..41
        const float2* pin = sxy + row * SP + cg * 8;
        float as[8], ad[8], as2[8], ad2[8];
        #pragma unroll
        for (int i = 0; i < 18; i++) {
            float2 v = pin[i];
            float ss = v.x * v.x;
            float dd = v.y * v.y;
            #pragma unroll
            for (int k = 0; k < 8; k++) {
                const int d = i - k;
                if (d == 0) {                 // first tap: mul-init (no MOV 0)
                    as[k]  = v.x * GW[0];
                    ad[k]  = v.y * GW[0];
                    as2[k] = ss  * GW[0];
                    ad2[k] = dd  * GW[0];
                } else if (d > 0 && d <= 10) {
                    const float w = GW[d];
                    as[k]  = fmaf(v.x, w, as[k]);
                    ad[k]  = fmaf(v.y, w, ad[k]);
                    as2[k] = fmaf(ss,  w, as2[k]);
                    ad2[k] = fmaf(dd,  w, ad2[k]);
                }
            }
        }
        const int hb = row * HP + cg * 8;
        #pragma unroll
        for (int k = 0; k < 8; k++)
            Hmap[hb + k] = make_float4(as[k], ad[k], as2[k], ad2[k]);
    }
    __syncthreads();

    // ---- Phase 3: vertical pass + SSIM, 4 rows per thread ----
    // Load bank audit (LDS.128): lane c -> word 4c, conflict-free per wavefront.
    const int c     = tid & 31;
    const int rbase = (tid >> 5) * 4;
    float ms[4], md[4], mss[4], mdd[4];
    const float4* p = Hmap + rbase * HP + c;
    #pragma unroll
    for (int j = 0; j < 14; j++) {
        float4 h = p[j * HP];
        #pragma unroll
        for (int k = 0; k < 4; k++) {
            const int d = j - k;
            if (d == 0) {
                ms[k]  = h.x * GW[0];
                md[k]  = h.y * GW[0];
                mss[k] = h.z * GW[0];
                mdd[k] = h.w * GW[0];
            } else if (d > 0 && d <= 10) {
                const float w = GW[d];
                ms[k]  = fmaf(h.x, w, ms[k]);
                md[k]  = fmaf(h.y, w, md[k]);
                mss[k] = fmaf(h.z, w, mss[k]);
                mdd[k] = fmaf(h.w, w, mdd[k]);
            }
        }
    }

    // SSIM in sum/diff-native form:
    //   a = mus^2-mud^2 (=4 mux*muy)      b = mus^2+mud^2 (=2(mux^2+muy^2))
    //   e = Ess-Edd     (=4 E[xy])        f = Ess+Edd     (=2(E[x^2]+E[y^2]))
    float lsum = 0.0f;
    #pragma unroll
    for (int k = 0; k < 4; k++) {
        float mus = ms[k],  mud = md[k];
        float a = fmaf(mus, mus, -(mud * mud));
        float b = fmaf(mus, mus,  (mud * mud));
        float e = mss[k] - mdd[k];
        float f = mss[k] + mdd[k];
        float n   = fmaf(0.5f, a, C1V) * fmaf(0.5f, e - a, C2V);
        float den = fmaf(0.5f, b, C1V) * fmaf(0.5f, f - b, C2V) + EPSV;
        float v = fmaf(__fdividef(n, den), 0.5f, 0.5f);
        v = fminf(fmaxf(v, 0.0f), 1.0f);
        lsum += v;
    }

    // ---- Reduction: warp shuffle -> smem -> block -> atomic ----
    #pragma unroll
    for (int off = 16; off > 0; off >>= 1)
        lsum += __shfl_xor_sync(0xFFFFFFFFu, lsum, off);
    if ((tid & 31) == 0) red[tid >> 5] = lsum;
    __syncthreads();
    if (tid == 0) {
        float t = 0.0f;
        #pragma unroll
        for (int w = 0; w < 8; w++) t += red[w];
        atomicAdd(out, t * inv_n);
    }
}

extern "C" void kernel_launch(void* const* d_in, const int* in_sizes, int n_in,
                              void* d_out, int out_size)
{
    const float* x = (const float*)d_in[0];
    const float* y = (const float*)d_in[1];
    float* out = (float*)d_out;

    zero_out_kernel<<<1, 1>>>(out);

    dim3 grid(IMG_W / TX, IMG_H / TY, 16 * 3);   // 16 x 16 x 48
    const float inv_n = 1.0f / (float)(16 * 3 * IMG_H * IMG_W);
    ssim_kernel<<<grid, NT>>>(x, y, out, inv_n);
}